// round 2
// baseline (speedup 1.0000x reference)
#include <cuda_runtime.h>
#include <math.h>

#define BB    64
#define NPTS  2048
#define SDIR  512
#define NDIRS 1536
#define QQ    1024
#define T0D   286
#define T1D   165
#define T2D   84
#define NSH   36

// exp(-d2/SIGMA2) with SIGMA2 = 0.08 -> 1/SIGMA2 = 12.5
// C1 = 12.5 * log2(e), C2 = 2*C1
#define C1F 18.0336880111120430f
#define C2F 36.0673760222240860f

__constant__ int c_pidx[36] = {
    0, 2, 5, 8, 12, 17, 22, 27, 32,
    38, 45, 52, 59, 66, 73, 80,
    88, 97, 106, 115, 124, 133, 142, 151, 160,
    170, 181, 192, 203, 214, 225, 236, 247, 258, 269, 280};
__constant__ float c_radii[3] = {0.4f, 0.8f, 1.2f};

// ---------------- scratch (static device globals; no allocation) ----------------
__device__ float4 g_xp[BB * NPTS];         // premultiplied points + log-weight
__device__ float  g_f[BB * NDIRS];         // shell densities
__device__ float  g_sh[BB * NSH * 3];      // SH coeffs, [b][j][shell]
__device__ float  g_E0[QQ * NSH];          // gathered D_eval0 columns
__device__ float  g_rs0[QQ];               // rowsums of D_eval0
__device__ float  g_z0[BB * NSH * 16];
__device__ float  g_Y[BB * QQ * 64];       // big eval buffer (reused all layers)
__device__ float  g_t1[BB * T1D * 16];
__device__ float  g_z1[BB * T1D * 32];
__device__ float  g_t2[BB * T2D * 32];
__device__ float  g_z2[BB * T2D * 64];
__device__ float  g_t3[BB * T2D * 64];
__device__ float  g_part[2 * 256 * 64];    // BN partial sums / sumsq
__device__ float  g_scale[64];             // folded BN scale
__device__ float  g_shift[64];             // folded BN shift
__device__ float  g_h[BB * 256];
__device__ float  g_a1[BB * 512];
__device__ float  g_a2[BB * 256];

__device__ __forceinline__ float ex2(float x) {
    float y;
    asm("ex2.approx.ftz.f32 %0, %1;" : "=f"(y) : "f"(x));
    return y;
}

// ---------------- point prep: x' = x*C2, w = -C1*|x|^2 ----------------
__global__ void k_prep(const float* __restrict__ x) {
    int i = blockIdx.x * blockDim.x + threadIdx.x;
    if (i >= BB * NPTS) return;
    float a = x[3 * i], b = x[3 * i + 1], c = x[3 * i + 2];
    float n2 = a * a + b * b + c * c;
    g_xp[i] = make_float4(a * C2F, b * C2F, c * C2F, -C1F * n2);
}

// ---------------- gather E0 + rowsums of D_eval0 ----------------
__global__ void k_e0prep(const float* __restrict__ D0) {
    int q = blockIdx.x * blockDim.x + threadIdx.x;
    if (q >= QQ) return;
    const float* row = D0 + q * T0D;
    float s = 0.f;
    for (int t = 0; t < T0D; t++) s += row[t];
    g_rs0[q] = s;
    for (int j = 0; j < NSH; j++) g_E0[q * NSH + j] = row[c_pidx[j]];
}

// ---------------- shell densities: f[b,s] = 2^{-c1 r^2}/N * sum_n exp2(x'.c + w) ----------------
__global__ void __launch_bounds__(256) k_shell(const float* __restrict__ dirs) {
    __shared__ float4 sp[NPTS];  // 32 KB
    int b = blockIdx.y;
    int s = blockIdx.x * 256 + threadIdx.x;  // 0..1535
    const float4* src = g_xp + b * NPTS;
    for (int i = threadIdx.x; i < NPTS; i += 256) sp[i] = src[i];
    __syncthreads();

    int shell = s >> 9;
    int j = s & 511;
    float r = c_radii[shell];
    const float* d = dirs + (size_t)(shell * SDIR + j) * 3;
    float cx = d[0] * r, cy = d[1] * r, cz = d[2] * r;
    float acc0 = 0.f, acc1 = 0.f;
#pragma unroll 8
    for (int i = 0; i < NPTS; i += 2) {
        float4 p = sp[i];
        float4 q = sp[i + 1];
        float t0 = fmaf(p.x, cx, fmaf(p.y, cy, fmaf(p.z, cz, p.w)));
        float t1 = fmaf(q.x, cx, fmaf(q.y, cy, fmaf(q.z, cz, q.w)));
        acc0 += ex2(t0);
        acc1 += ex2(t1);
    }
    float sc = ex2(-C1F * r * r) * (1.0f / (float)NPTS);
    g_f[b * NDIRS + s] = (acc0 + acc1) * sc;
}

// ---------------- SH projection: sh[b,j,i] = sum_s f[b,i,s] * A_sh[j,s] ----------------
__global__ void k_shproj(const float* __restrict__ A_sh) {
    int b = blockIdx.x;
    __shared__ float fs[NDIRS];
    for (int i = threadIdx.x; i < NDIRS; i += blockDim.x) fs[i] = g_f[b * NDIRS + i];
    __syncthreads();
    int o = threadIdx.x;
    if (o < 108) {
        int shell = o / NSH;
        int j = o % NSH;
        const float* arow = A_sh + j * SDIR;
        const float* f = fs + shell * SDIR;
        float acc0 = 0.f, acc1 = 0.f;
#pragma unroll 8
        for (int s = 0; s < SDIR; s += 2) {
            acc0 = fmaf(arow[s], f[s], acc0);
            acc1 = fmaf(arow[s + 1], f[s + 1], acc1);
        }
        g_sh[(b * NSH + j) * 3 + shell] = acc0 + acc1;
    }
}

// ---------------- channel mix: out[bt,u] = sum_c in[bt,c]*W[c,u] (+bias) ----------------
__global__ void k_mix(const float* __restrict__ in, const float* __restrict__ W,
                      const float* __restrict__ bias, float* __restrict__ out,
                      int T, int Cin, int U) {
    int i = blockIdx.x * 256 + threadIdx.x;
    if (i >= BB * T * U) return;
    int u = i % U;
    int bt = i / U;
    const float* row = in + (size_t)bt * Cin;
    float acc = bias ? bias[u] : 0.f;
    for (int c = 0; c < Cin; c++) acc = fmaf(row[c], W[c * U + u], acc);
    out[i] = acc;
}

// ---------------- tiled GEMM: C[b] = A[M,K] @ act(B[b][K,N]) (+rowsum[m]*bias[u]) ----------------
template <int N>
__global__ void __launch_bounds__(256) k_gemm(
    const float* __restrict__ A, const float* __restrict__ Bm, float* __restrict__ C,
    int M, int K,
    const float* __restrict__ sc, const float* __restrict__ sh,
    const float* __restrict__ rowsum, const float* __restrict__ bias) {
    constexpr int TM = 1024 / N;
    constexpr int MG = 256 / N;
    constexpr int RM = 4;
    __shared__ float As[TM * 33];
    __shared__ float Bs[32 * N];
    int b = blockIdx.y;
    int m0 = blockIdx.x * TM;
    int t = threadIdx.x;
    int u = t % N;
    int mg = t / N;
    const float* Bb = Bm + (size_t)b * K * N;
    float acc[RM] = {0.f, 0.f, 0.f, 0.f};

    for (int k0 = 0; k0 < K; k0 += 32) {
        // A tile
        for (int e = t; e < TM * 32; e += 256) {
            int row = e >> 5, col = e & 31;
            int m = m0 + row, k = k0 + col;
            As[row * 33 + col] = (m < M && k < K) ? A[(size_t)m * K + k] : 0.f;
        }
        // B tile (with optional folded BN + LeakyReLU)
        for (int e = t; e < 32 * N; e += 256) {
            int kk = e / N, uu = e % N;
            int k = k0 + kk;
            float v = 0.f;
            if (k < K) {
                v = Bb[(size_t)k * N + uu];
                if (sc) {
                    v = fmaf(v, sc[uu], sh[uu]);
                    v = fmaxf(v, 0.3f * v);
                }
            }
            Bs[kk * N + uu] = v;
        }
        __syncthreads();
#pragma unroll
        for (int kk = 0; kk < 32; kk++) {
            float bv = Bs[kk * N + u];
#pragma unroll
            for (int i = 0; i < RM; i++)
                acc[i] = fmaf(As[(mg + i * MG) * 33 + kk], bv, acc[i]);
        }
        __syncthreads();
    }
#pragma unroll
    for (int i = 0; i < RM; i++) {
        int m = m0 + mg + i * MG;
        if (m < M) {
            float v = acc[i];
            if (rowsum) v = fmaf(rowsum[m], bias[u], v);
            C[(size_t)b * M * N + m * N + u] = v;
        }
    }
}

// ---------------- BN stats (deterministic two-stage) ----------------
__global__ void k_stats_part(int U) {
    int t = threadIdx.x;
    int total = BB * QQ * U;
    float s = 0.f, sq = 0.f;
    for (int i = blockIdx.x * 256 + t; i < total; i += 256 * 256) {
        float v = g_Y[i];
        s += v;
        sq = fmaf(v, v, sq);
    }
    __shared__ float ss[256], qq[256];
    ss[t] = s; qq[t] = sq;
    __syncthreads();
    for (int st = 128; st >= U; st >>= 1) {
        if (t < st) { ss[t] += ss[t + st]; qq[t] += qq[t + st]; }
        __syncthreads();
    }
    if (t < U) {
        g_part[blockIdx.x * U + t] = ss[t];
        g_part[256 * 64 + blockIdx.x * U + t] = qq[t];
    }
}

__global__ void k_stats_fin(int U, const float* __restrict__ g, const float* __restrict__ be) {
    int u = blockIdx.x;
    int t = threadIdx.x;
    __shared__ float ss[256], qq[256];
    ss[t] = g_part[t * U + u];
    qq[t] = g_part[256 * 64 + t * U + u];
    __syncthreads();
    for (int st = 128; st > 0; st >>= 1) {
        if (t < st) { ss[t] += ss[t + st]; qq[t] += qq[t + st]; }
        __syncthreads();
    }
    if (t == 0) {
        const float inv = 1.0f / (float)(BB * QQ);
        float m = ss[0] * inv;
        float var = qq[0] * inv - m * m;
        float rs = rsqrtf(var + 1e-3f);
        float scv = rs * g[u];
        g_scale[u] = scv;
        g_shift[u] = be[u] - m * scv;
    }
}

// ---------------- degree-wise norms -> h[b,256] ----------------
__global__ void k_norm() {
    int b = blockIdx.x;
    int t = threadIdx.x;
    int blk = t >> 6;
    int u = t & 63;
    int off, sz;
    if (blk == 0)      { off = 0;  sz = 1; }
    else if (blk == 1) { off = 1;  sz = 9; }
    else if (blk == 2) { off = 10; sz = 25; }
    else               { off = 35; sz = 49; }
    const float* y = g_t3 + (size_t)b * T2D * 64;
    float s = 0.f;
    for (int r = 0; r < sz; r++) {
        float v = y[(off + r) * 64 + u];
        s = fmaf(v, v, s);
    }
    g_h[b * 256 + t] = sqrtf(s);
}

// ---------------- dense FC: out[b,j] = sum_i in[b,i]*W[i,j] + bias[j] ----------------
__global__ void k_fc(const float* __restrict__ in, const float* __restrict__ W,
                     const float* __restrict__ bias, float* __restrict__ out,
                     int IN, int OUT) {
    __shared__ float s[512];
    int b = blockIdx.x;
    for (int i = threadIdx.x; i < IN; i += blockDim.x) s[i] = in[b * IN + i];
    __syncthreads();
    int j = threadIdx.x;
    if (j < OUT) {
        float acc = bias[j];
        for (int i = 0; i < IN; i++) acc = fmaf(s[i], W[i * OUT + j], acc);
        out[b * OUT + j] = acc;
    }
}

// ---------------- batch BN (over 64 samples) + ReLU, in place ----------------
__global__ void k_bnrelu(float* __restrict__ a, const float* __restrict__ g,
                         const float* __restrict__ be, int F) {
    int j = blockIdx.x;
    int b = threadIdx.x;  // 64
    float v = a[b * F + j];
    __shared__ float ss[64], qq[64];
    __shared__ float sm, sr;
    ss[b] = v; qq[b] = v * v;
    __syncthreads();
    for (int st = 32; st > 0; st >>= 1) {
        if (b < st) { ss[b] += ss[b + st]; qq[b] += qq[b + st]; }
        __syncthreads();
    }
    if (b == 0) {
        float m = ss[0] * (1.0f / 64.0f);
        float var = qq[0] * (1.0f / 64.0f) - m * m;
        sm = m;
        sr = rsqrtf(var + 1e-3f);
    }
    __syncthreads();
    float y = (v - sm) * sr * g[j] + be[j];
    a[b * F + j] = y > 0.f ? y : 0.f;
}

// ---------------- output head + softmax ----------------
__global__ void k_out(const float* __restrict__ Wout, const float* __restrict__ bout,
                      float* __restrict__ out) {
    int b = blockIdx.x;
    __shared__ float h[256];
    __shared__ float lg[40];
    for (int i = threadIdx.x; i < 256; i += 64) h[i] = g_a2[b * 256 + i];
    __syncthreads();
    if (threadIdx.x < 40) {
        float acc = bout[threadIdx.x];
        for (int i = 0; i < 256; i++) acc = fmaf(h[i], Wout[i * 40 + threadIdx.x], acc);
        lg[threadIdx.x] = acc;
    }
    __syncthreads();
    if (threadIdx.x == 0) {
        float mx = -1e30f;
        for (int i = 0; i < 40; i++) mx = fmaxf(mx, lg[i]);
        float s = 0.f;
        for (int i = 0; i < 40; i++) {
            float e = __expf(lg[i] - mx);
            lg[i] = e;
            s += e;
        }
        float inv = 1.f / s;
        for (int i = 0; i < 40; i++) out[b * 40 + i] = lg[i] * inv;
    }
}

// ---------------- launch ----------------
extern "C" void kernel_launch(void* const* d_in, const int* in_sizes, int n_in,
                              void* d_out, int out_size) {
    const float* x          = (const float*)d_in[0];
    const float* shell_dirs = (const float*)d_in[1];
    const float* A_sh       = (const float*)d_in[2];
    const float* D_eval0    = (const float*)d_in[3];
    const float* D_eval1    = (const float*)d_in[4];
    const float* D_eval2    = (const float*)d_in[5];
    const float* D_coef1    = (const float*)d_in[6];
    const float* D_coef2    = (const float*)d_in[7];
    const float* D_coefL    = (const float*)d_in[8];
    const float* W0 = (const float*)d_in[9];   const float* b0 = (const float*)d_in[10];
    const float* W1 = (const float*)d_in[11];  const float* b1 = (const float*)d_in[12];
    const float* W2 = (const float*)d_in[13];  const float* b2 = (const float*)d_in[14];
    const float* g0 = (const float*)d_in[15];  const float* be0 = (const float*)d_in[16];
    const float* g1 = (const float*)d_in[17];  const float* be1 = (const float*)d_in[18];
    const float* g2 = (const float*)d_in[19];  const float* be2 = (const float*)d_in[20];
    const float* Wfc1 = (const float*)d_in[21]; const float* bfc1 = (const float*)d_in[22];
    const float* gfc1 = (const float*)d_in[23]; const float* befc1 = (const float*)d_in[24];
    const float* Wfc2 = (const float*)d_in[25]; const float* bfc2 = (const float*)d_in[26];
    const float* gfc2 = (const float*)d_in[27]; const float* befc2 = (const float*)d_in[28];
    const float* Wout = (const float*)d_in[29]; const float* bout = (const float*)d_in[30];
    float* out = (float*)d_out;

    float *pE0, *prs0, *psh, *pz0, *pY, *pt1, *pz1, *pt2, *pz2, *pt3, *psc, *pshf, *ph, *pa1, *pa2;
    cudaGetSymbolAddress((void**)&pE0, g_E0);
    cudaGetSymbolAddress((void**)&prs0, g_rs0);
    cudaGetSymbolAddress((void**)&psh, g_sh);
    cudaGetSymbolAddress((void**)&pz0, g_z0);
    cudaGetSymbolAddress((void**)&pY, g_Y);
    cudaGetSymbolAddress((void**)&pt1, g_t1);
    cudaGetSymbolAddress((void**)&pz1, g_z1);
    cudaGetSymbolAddress((void**)&pt2, g_t2);
    cudaGetSymbolAddress((void**)&pz2, g_z2);
    cudaGetSymbolAddress((void**)&pt3, g_t3);
    cudaGetSymbolAddress((void**)&psc, g_scale);
    cudaGetSymbolAddress((void**)&pshf, g_shift);
    cudaGetSymbolAddress((void**)&ph, g_h);
    cudaGetSymbolAddress((void**)&pa1, g_a1);
    cudaGetSymbolAddress((void**)&pa2, g_a2);

    // shell embedding
    k_prep<<<(BB * NPTS + 255) / 256, 256>>>(x);
    k_e0prep<<<4, 256>>>(D_eval0);
    k_shell<<<dim3(6, BB), 256>>>(shell_dirs);
    k_shproj<<<BB, 128>>>(A_sh);

    // layer 0
    k_mix<<<(BB * NSH * 16 + 255) / 256, 256>>>(psh, W0, nullptr, pz0, NSH, 3, 16);
    k_gemm<16><<<dim3(16, BB), 256>>>(pE0, pz0, pY, QQ, NSH, nullptr, nullptr, prs0, b0);
    k_stats_part<<<256, 256>>>(16);
    k_stats_fin<<<16, 256>>>(16, g0, be0);
    k_gemm<16><<<dim3(3, BB), 256>>>(D_coef1, pY, pt1, T1D, QQ, psc, pshf, nullptr, nullptr);

    // layer 1
    k_mix<<<(BB * T1D * 32 + 255) / 256, 256>>>(pt1, W1, b1, pz1, T1D, 16, 32);
    k_gemm<32><<<dim3(32, BB), 256>>>(D_eval1, pz1, pY, QQ, T1D, nullptr, nullptr, nullptr, nullptr);
    k_stats_part<<<256, 256>>>(32);
    k_stats_fin<<<32, 256>>>(32, g1, be1);
    k_gemm<32><<<dim3(3, BB), 256>>>(D_coef2, pY, pt2, T2D, QQ, psc, pshf, nullptr, nullptr);

    // layer 2
    k_mix<<<(BB * T2D * 64 + 255) / 256, 256>>>(pt2, W2, b2, pz2, T2D, 32, 64);
    k_gemm<64><<<dim3(64, BB), 256>>>(D_eval2, pz2, pY, QQ, T2D, nullptr, nullptr, nullptr, nullptr);
    k_stats_part<<<256, 256>>>(64);
    k_stats_fin<<<64, 256>>>(64, g2, be2);
    k_gemm<64><<<dim3(6, BB), 256>>>(D_coefL, pY, pt3, T2D, QQ, psc, pshf, nullptr, nullptr);

    // pooling + head
    k_norm<<<BB, 256>>>();
    k_fc<<<BB, 512>>>(ph, Wfc1, bfc1, pa1, 256, 512);
    k_bnrelu<<<512, 64>>>(pa1, gfc1, befc1, 512);
    k_fc<<<BB, 256>>>(pa1, Wfc2, bfc2, pa2, 512, 256);
    k_bnrelu<<<256, 64>>>(pa2, gfc2, befc2, 256);
    k_out<<<BB, 64>>>(Wout, bout, out);
}

// round 3
// speedup vs baseline: 1.1432x; 1.1432x over previous
#include <cuda_runtime.h>
#include <math.h>

#define BB    64
#define NPTS  2048
#define SDIR  512
#define NDIRS 1536
#define QQ    1024
#define T0D   286
#define T1D   165
#define T2D   84
#define NSH   36

// exp(-d2/SIGMA2) with SIGMA2 = 0.08 -> 1/SIGMA2 = 12.5
// C1 = 12.5 * log2(e), C2 = 2*C1
#define C1F 18.0336880111120430f
#define C2F 36.0673760222240860f

__constant__ int c_pidx[36] = {
    0, 2, 5, 8, 12, 17, 22, 27, 32,
    38, 45, 52, 59, 66, 73, 80,
    88, 97, 106, 115, 124, 133, 142, 151, 160,
    170, 181, 192, 203, 214, 225, 236, 247, 258, 269, 280};
__constant__ float c_radii[3] = {0.4f, 0.8f, 1.2f};

// ---------------- scratch (static device globals; no allocation) ----------------
__device__ float4 g_xp[BB * NPTS];         // premultiplied points + log-weight
__device__ float  g_f[BB * NDIRS];         // shell densities
__device__ float  g_sh[BB * NSH * 3];      // SH coeffs, [b][j][shell]
__device__ float  g_E0[QQ * NSH];          // gathered D_eval0 columns
__device__ float  g_rs0[QQ];               // rowsums of D_eval0
__device__ float  g_z0[BB * NSH * 16];
__device__ float  g_Y[BB * QQ * 64];       // big eval buffer (reused all layers)
__device__ float  g_t1[BB * T1D * 16];
__device__ float  g_z1[BB * T1D * 32];
__device__ float  g_t2[BB * T2D * 32];
__device__ float  g_z2[BB * T2D * 64];
__device__ float  g_t3[BB * T2D * 64];
__device__ float  g_part[2 * 256 * 64];    // BN partial sums / sumsq
__device__ float  g_scale[64];             // folded BN scale
__device__ float  g_shift[64];             // folded BN shift
__device__ float  g_h[BB * 256];
__device__ float  g_a1[BB * 512];
__device__ float  g_a2[BB * 256];

__device__ __forceinline__ float ex2(float x) {
    float y;
    asm("ex2.approx.ftz.f32 %0, %1;" : "=f"(y) : "f"(x));
    return y;
}

// ---------------- point prep: x' = x*C2, w = -C1*|x|^2 ----------------
__global__ void k_prep(const float* __restrict__ x) {
    int i = blockIdx.x * blockDim.x + threadIdx.x;
    if (i >= BB * NPTS) return;
    float a = x[3 * i], b = x[3 * i + 1], c = x[3 * i + 2];
    float n2 = a * a + b * b + c * c;
    g_xp[i] = make_float4(a * C2F, b * C2F, c * C2F, -C1F * n2);
}

// ---------------- gather E0 + rowsums of D_eval0 ----------------
__global__ void k_e0prep(const float* __restrict__ D0) {
    int q = blockIdx.x * blockDim.x + threadIdx.x;
    if (q >= QQ) return;
    const float* row = D0 + q * T0D;
    float s = 0.f;
    for (int t = 0; t < T0D; t++) s += row[t];
    g_rs0[q] = s;
    for (int j = 0; j < NSH; j++) g_E0[q * NSH + j] = row[c_pidx[j]];
}

// ---------------- shell densities: f[b,s] = 2^{-c1 r^2}/N * sum_n exp2(x'.c + w) ----------------
__global__ void __launch_bounds__(256) k_shell(const float* __restrict__ dirs) {
    __shared__ float4 sp[NPTS];  // 32 KB
    int b = blockIdx.y;
    int s = blockIdx.x * 256 + threadIdx.x;  // 0..1535
    const float4* src = g_xp + b * NPTS;
    for (int i = threadIdx.x; i < NPTS; i += 256) sp[i] = src[i];
    __syncthreads();

    int shell = s >> 9;
    int j = s & 511;
    float r = c_radii[shell];
    const float* d = dirs + (size_t)(shell * SDIR + j) * 3;
    float cx = d[0] * r, cy = d[1] * r, cz = d[2] * r;
    float acc0 = 0.f, acc1 = 0.f;
#pragma unroll 8
    for (int i = 0; i < NPTS; i += 2) {
        float4 p = sp[i];
        float4 q = sp[i + 1];
        float t0 = fmaf(p.x, cx, fmaf(p.y, cy, fmaf(p.z, cz, p.w)));
        float t1 = fmaf(q.x, cx, fmaf(q.y, cy, fmaf(q.z, cz, q.w)));
        acc0 += ex2(t0);
        acc1 += ex2(t1);
    }
    float sc = ex2(-C1F * r * r) * (1.0f / (float)NPTS);
    g_f[b * NDIRS + s] = (acc0 + acc1) * sc;
}

// ---------------- SH projection, warp-per-output ----------------
// out[b, j, shell] = sum_s A_sh[j,s] * f[b, shell*512 + s]
__global__ void k_shproj(const float* __restrict__ A_sh) {
    int w = blockIdx.x * 8 + (threadIdx.x >> 5);   // global warp id, 0..6911
    int l = threadIdx.x & 31;
    int b = w / 108;
    int o = w % 108;
    int shell = o / NSH;
    int j = o % NSH;
    const float* arow = A_sh + j * SDIR;
    const float* f = g_f + b * NDIRS + shell * SDIR;
    float acc = 0.f;
#pragma unroll
    for (int s = l; s < SDIR; s += 32) acc = fmaf(arow[s], f[s], acc);
#pragma unroll
    for (int st = 16; st > 0; st >>= 1)
        acc += __shfl_xor_sync(0xffffffffu, acc, st);
    if (l == 0) g_sh[(b * NSH + j) * 3 + shell] = acc;
}

// ---------------- channel mix: out[bt,u] = sum_c in[bt,c]*W[c,u] (+bias) ----------------
__global__ void k_mix(const float* __restrict__ in, const float* __restrict__ W,
                      const float* __restrict__ bias, float* __restrict__ out,
                      int T, int Cin, int U) {
    int i = blockIdx.x * 256 + threadIdx.x;
    if (i >= BB * T * U) return;
    int u = i % U;
    int bt = i / U;
    const float* row = in + (size_t)bt * Cin;
    float acc = bias ? bias[u] : 0.f;
    for (int c = 0; c < Cin; c++) acc = fmaf(row[c], W[c * U + u], acc);
    out[i] = acc;
}

// ---------------- 2D register-tiled GEMM ----------------
// C[bb][m][u] = sum_k A[m][k] * act(B[bb][k][u])  (+ rowsum[m]*bias[u])
// Block: 256 threads (16x16), each computes 4x4 outputs. Tile: M=64, Ne=N*NB=64.
// NB batches packed along the N direction of the tile; A shared across batches.
template <int N, int NB>
__global__ void __launch_bounds__(256) k_gemm2(
    const float* __restrict__ A, const float* __restrict__ Bm, float* __restrict__ C,
    int M, int K,
    const float* __restrict__ sc, const float* __restrict__ sh,
    const float* __restrict__ rowsum, const float* __restrict__ bias) {
    constexpr int NE = N * NB;      // 64
    __shared__ __align__(16) float As[32][72];  // [k][m], padded
    __shared__ __align__(16) float Bs[32][NE];  // [k][uu]
    int t = threadIdx.x;
    int tx = t & 15, ty = t >> 4;
    int m0 = blockIdx.x * 64;
    int bgrp = blockIdx.y * NB;
    float acc[4][4];
#pragma unroll
    for (int i = 0; i < 4; i++)
#pragma unroll
        for (int jj = 0; jj < 4; jj++) acc[i][jj] = 0.f;

    for (int k0 = 0; k0 < K; k0 += 32) {
        // A tile: load A[m0+row][k0+col] -> As[col][row]
#pragma unroll
        for (int e = 0; e < 8; e++) {
            int idx = t + e * 256;             // 0..2047
            int row = idx >> 5, col = idx & 31;
            int m = m0 + row, k = k0 + col;
            As[col][row] = (m < M && k < K) ? A[(size_t)m * K + k] : 0.f;
        }
        // B tile: load Bm[bb][k0+kk][u] -> Bs[kk][uu], with folded BN+LReLU if sc
#pragma unroll
        for (int e = 0; e < (32 * NE) / 256; e++) {
            int idx = t + e * 256;
            int kk = idx / NE, uu = idx % NE;
            int k = k0 + kk;
            float v = 0.f;
            if (k < K) {
                int bb = bgrp + uu / N;
                int u = uu % N;
                v = Bm[((size_t)bb * K + k) * N + u];
                if (sc) {
                    v = fmaf(v, sc[u], sh[u]);
                    v = fmaxf(v, 0.3f * v);
                }
            }
            Bs[kk][uu] = v;
        }
        __syncthreads();
#pragma unroll 8
        for (int kk = 0; kk < 32; kk++) {
            float4 a = *reinterpret_cast<const float4*>(&As[kk][ty * 4]);
            float4 bv = *reinterpret_cast<const float4*>(&Bs[kk][tx * 4]);
            float av[4] = {a.x, a.y, a.z, a.w};
            float bw[4] = {bv.x, bv.y, bv.z, bv.w};
#pragma unroll
            for (int i = 0; i < 4; i++)
#pragma unroll
                for (int jj = 0; jj < 4; jj++)
                    acc[i][jj] = fmaf(av[i], bw[jj], acc[i][jj]);
        }
        __syncthreads();
    }

    // epilogue
    int uu0 = tx * 4;
    int bb = bgrp + uu0 / N;     // 4 consecutive cols stay within one batch (4 | N)
    int ub = uu0 % N;
#pragma unroll
    for (int i = 0; i < 4; i++) {
        int m = m0 + ty * 4 + i;
        if (m < M) {
            float rs = rowsum ? rowsum[m] : 0.f;
#pragma unroll
            for (int jj = 0; jj < 4; jj++) {
                float v = acc[i][jj];
                if (rowsum) v = fmaf(rs, bias[ub + jj], v);
                C[((size_t)bb * M + m) * N + ub + jj] = v;
            }
        }
    }
}

// ---------------- BN stats (deterministic two-stage) ----------------
__global__ void k_stats_part(int U) {
    int t = threadIdx.x;
    int total = BB * QQ * U;
    float s = 0.f, sq = 0.f;
    for (int i = blockIdx.x * 256 + t; i < total; i += 256 * 256) {
        float v = g_Y[i];
        s += v;
        sq = fmaf(v, v, sq);
    }
    __shared__ float ss[256], qq[256];
    ss[t] = s; qq[t] = sq;
    __syncthreads();
    for (int st = 128; st >= U; st >>= 1) {
        if (t < st) { ss[t] += ss[t + st]; qq[t] += qq[t + st]; }
        __syncthreads();
    }
    if (t < U) {
        g_part[blockIdx.x * U + t] = ss[t];
        g_part[256 * 64 + blockIdx.x * U + t] = qq[t];
    }
}

__global__ void k_stats_fin(int U, const float* __restrict__ g, const float* __restrict__ be) {
    int u = blockIdx.x;
    int t = threadIdx.x;
    __shared__ float ss[256], qq[256];
    ss[t] = g_part[t * U + u];
    qq[t] = g_part[256 * 64 + t * U + u];
    __syncthreads();
    for (int st = 128; st > 0; st >>= 1) {
        if (t < st) { ss[t] += ss[t + st]; qq[t] += qq[t + st]; }
        __syncthreads();
    }
    if (t == 0) {
        const float inv = 1.0f / (float)(BB * QQ);
        float m = ss[0] * inv;
        float var = qq[0] * inv - m * m;
        float rs = rsqrtf(var + 1e-3f);
        float scv = rs * g[u];
        g_scale[u] = scv;
        g_shift[u] = be[u] - m * scv;
    }
}

// ---------------- degree-wise norms -> h[b,256] ----------------
__global__ void k_norm() {
    int b = blockIdx.x;
    int t = threadIdx.x;
    int blk = t >> 6;
    int u = t & 63;
    int off, sz;
    if (blk == 0)      { off = 0;  sz = 1; }
    else if (blk == 1) { off = 1;  sz = 9; }
    else if (blk == 2) { off = 10; sz = 25; }
    else               { off = 35; sz = 49; }
    const float* y = g_t3 + (size_t)b * T2D * 64;
    float s = 0.f;
    for (int r = 0; r < sz; r++) {
        float v = y[(off + r) * 64 + u];
        s = fmaf(v, v, s);
    }
    g_h[b * 256 + t] = sqrtf(s);
}

// ---------------- dense FC: out[b,j] = sum_i in[b,i]*W[i,j] + bias[j] ----------------
__global__ void k_fc(const float* __restrict__ in, const float* __restrict__ W,
                     const float* __restrict__ bias, float* __restrict__ out,
                     int IN, int OUT) {
    __shared__ float s[512];
    int b = blockIdx.x;
    for (int i = threadIdx.x; i < IN; i += blockDim.x) s[i] = in[b * IN + i];
    __syncthreads();
    int j = threadIdx.x;
    if (j < OUT) {
        float acc = bias[j];
        for (int i = 0; i < IN; i++) acc = fmaf(s[i], W[i * OUT + j], acc);
        out[b * OUT + j] = acc;
    }
}

// ---------------- batch BN (over 64 samples) + ReLU, in place ----------------
__global__ void k_bnrelu(float* __restrict__ a, const float* __restrict__ g,
                         const float* __restrict__ be, int F) {
    int j = blockIdx.x;
    int b = threadIdx.x;  // 64
    float v = a[b * F + j];
    __shared__ float ss[64], qq[64];
    __shared__ float sm, sr;
    ss[b] = v; qq[b] = v * v;
    __syncthreads();
    for (int st = 32; st > 0; st >>= 1) {
        if (b < st) { ss[b] += ss[b + st]; qq[b] += qq[b + st]; }
        __syncthreads();
    }
    if (b == 0) {
        float m = ss[0] * (1.0f / 64.0f);
        float var = qq[0] * (1.0f / 64.0f) - m * m;
        sm = m;
        sr = rsqrtf(var + 1e-3f);
    }
    __syncthreads();
    float y = (v - sm) * sr * g[j] + be[j];
    a[b * F + j] = y > 0.f ? y : 0.f;
}

// ---------------- output head + softmax ----------------
__global__ void k_out(const float* __restrict__ Wout, const float* __restrict__ bout,
                      float* __restrict__ out) {
    int b = blockIdx.x;
    __shared__ float h[256];
    __shared__ float lg[40];
    for (int i = threadIdx.x; i < 256; i += 64) h[i] = g_a2[b * 256 + i];
    __syncthreads();
    if (threadIdx.x < 40) {
        float acc = bout[threadIdx.x];
        for (int i = 0; i < 256; i++) acc = fmaf(h[i], Wout[i * 40 + threadIdx.x], acc);
        lg[threadIdx.x] = acc;
    }
    __syncthreads();
    if (threadIdx.x == 0) {
        float mx = -1e30f;
        for (int i = 0; i < 40; i++) mx = fmaxf(mx, lg[i]);
        float s = 0.f;
        for (int i = 0; i < 40; i++) {
            float e = __expf(lg[i] - mx);
            lg[i] = e;
            s += e;
        }
        float inv = 1.f / s;
        for (int i = 0; i < 40; i++) out[b * 40 + i] = lg[i] * inv;
    }
}

// ---------------- launch ----------------
extern "C" void kernel_launch(void* const* d_in, const int* in_sizes, int n_in,
                              void* d_out, int out_size) {
    const float* x          = (const float*)d_in[0];
    const float* shell_dirs = (const float*)d_in[1];
    const float* A_sh       = (const float*)d_in[2];
    const float* D_eval0    = (const float*)d_in[3];
    const float* D_eval1    = (const float*)d_in[4];
    const float* D_eval2    = (const float*)d_in[5];
    const float* D_coef1    = (const float*)d_in[6];
    const float* D_coef2    = (const float*)d_in[7];
    const float* D_coefL    = (const float*)d_in[8];
    const float* W0 = (const float*)d_in[9];   const float* b0 = (const float*)d_in[10];
    const float* W1 = (const float*)d_in[11];  const float* b1 = (const float*)d_in[12];
    const float* W2 = (const float*)d_in[13];  const float* b2 = (const float*)d_in[14];
    const float* g0 = (const float*)d_in[15];  const float* be0 = (const float*)d_in[16];
    const float* g1 = (const float*)d_in[17];  const float* be1 = (const float*)d_in[18];
    const float* g2 = (const float*)d_in[19];  const float* be2 = (const float*)d_in[20];
    const float* Wfc1 = (const float*)d_in[21]; const float* bfc1 = (const float*)d_in[22];
    const float* gfc1 = (const float*)d_in[23]; const float* befc1 = (const float*)d_in[24];
    const float* Wfc2 = (const float*)d_in[25]; const float* bfc2 = (const float*)d_in[26];
    const float* gfc2 = (const float*)d_in[27]; const float* befc2 = (const float*)d_in[28];
    const float* Wout = (const float*)d_in[29]; const float* bout = (const float*)d_in[30];
    float* out = (float*)d_out;

    float *pE0, *prs0, *psh, *pz0, *pY, *pt1, *pz1, *pt2, *pz2, *pt3, *psc, *pshf, *ph, *pa1, *pa2;
    cudaGetSymbolAddress((void**)&pE0, g_E0);
    cudaGetSymbolAddress((void**)&prs0, g_rs0);
    cudaGetSymbolAddress((void**)&psh, g_sh);
    cudaGetSymbolAddress((void**)&pz0, g_z0);
    cudaGetSymbolAddress((void**)&pY, g_Y);
    cudaGetSymbolAddress((void**)&pt1, g_t1);
    cudaGetSymbolAddress((void**)&pz1, g_z1);
    cudaGetSymbolAddress((void**)&pt2, g_t2);
    cudaGetSymbolAddress((void**)&pz2, g_z2);
    cudaGetSymbolAddress((void**)&pt3, g_t3);
    cudaGetSymbolAddress((void**)&psc, g_scale);
    cudaGetSymbolAddress((void**)&pshf, g_shift);
    cudaGetSymbolAddress((void**)&ph, g_h);
    cudaGetSymbolAddress((void**)&pa1, g_a1);
    cudaGetSymbolAddress((void**)&pa2, g_a2);

    // shell embedding
    k_prep<<<(BB * NPTS + 255) / 256, 256>>>(x);
    k_e0prep<<<4, 256>>>(D_eval0);
    k_shell<<<dim3(6, BB), 256>>>(shell_dirs);
    k_shproj<<<864, 256>>>(A_sh);

    // layer 0
    k_mix<<<(BB * NSH * 16 + 255) / 256, 256>>>(psh, W0, nullptr, pz0, NSH, 3, 16);
    k_gemm2<16, 4><<<dim3(16, 16), 256>>>(pE0, pz0, pY, QQ, NSH, nullptr, nullptr, prs0, b0);
    k_stats_part<<<256, 256>>>(16);
    k_stats_fin<<<16, 256>>>(16, g0, be0);
    k_gemm2<16, 4><<<dim3(3, 16), 256>>>(D_coef1, pY, pt1, T1D, QQ, psc, pshf, nullptr, nullptr);

    // layer 1
    k_mix<<<(BB * T1D * 32 + 255) / 256, 256>>>(pt1, W1, b1, pz1, T1D, 16, 32);
    k_gemm2<32, 2><<<dim3(16, 32), 256>>>(D_eval1, pz1, pY, QQ, T1D, nullptr, nullptr, nullptr, nullptr);
    k_stats_part<<<256, 256>>>(32);
    k_stats_fin<<<32, 256>>>(32, g1, be1);
    k_gemm2<32, 2><<<dim3(2, 32), 256>>>(D_coef2, pY, pt2, T2D, QQ, psc, pshf, nullptr, nullptr);

    // layer 2
    k_mix<<<(BB * T2D * 64 + 255) / 256, 256>>>(pt2, W2, b2, pz2, T2D, 32, 64);
    k_gemm2<64, 1><<<dim3(16, 64), 256>>>(D_eval2, pz2, pY, QQ, T2D, nullptr, nullptr, nullptr, nullptr);
    k_stats_part<<<256, 256>>>(64);
    k_stats_fin<<<64, 256>>>(64, g2, be2);
    k_gemm2<64, 1><<<dim3(2, 64), 256>>>(D_coefL, pY, pt3, T2D, QQ, psc, pshf, nullptr, nullptr);

    // pooling + head
    k_norm<<<BB, 256>>>();
    k_fc<<<BB, 512>>>(ph, Wfc1, bfc1, pa1, 256, 512);
    k_bnrelu<<<512, 64>>>(pa1, gfc1, befc1, 512);
    k_fc<<<BB, 256>>>(pa1, Wfc2, bfc2, pa2, 512, 256);
    k_bnrelu<<<256, 64>>>(pa2, gfc2, befc2, 256);
    k_out<<<BB, 64>>>(Wout, bout, out);
}

// round 4
// speedup vs baseline: 1.9181x; 1.6778x over previous
#include <cuda_runtime.h>
#include <math.h>

#define BB    64
#define NPTS  2048
#define SDIR  512
#define NDIRS 1536
#define QQ    1024
#define T0D   286
#define T1D   165
#define T2D   84
#define NSH   36
#define SK    8

// exp(-d2/SIGMA2) with SIGMA2 = 0.08 -> 1/SIGMA2 = 12.5
// C1 = 12.5 * log2(e), C2 = 2*C1
#define C1F 18.0336880111120430f
#define C2F 36.0673760222240860f

__constant__ int c_pidx[36] = {
    0, 2, 5, 8, 12, 17, 22, 27, 32,
    38, 45, 52, 59, 66, 73, 80,
    88, 97, 106, 115, 124, 133, 142, 151, 160,
    170, 181, 192, 203, 214, 225, 236, 247, 258, 269, 280};
__constant__ float c_radii[3] = {0.4f, 0.8f, 1.2f};

// ---------------- scratch (static device globals; no allocation) ----------------
__device__ float4 g_xp[BB * NPTS];
__device__ float  g_f[BB * NDIRS];
__device__ float  g_sh[BB * NSH * 3];
__device__ float  g_E0[QQ * NSH];
__device__ float  g_rs0[QQ];
__device__ float  g_z0[BB * NSH * 16];
__device__ float  g_Y[BB * QQ * 64];
__device__ float  g_t1[BB * T1D * 16];
__device__ float  g_z1[BB * T1D * 32];
__device__ float  g_t2[BB * T2D * 32];
__device__ float  g_z2[BB * T2D * 64];
__device__ float  g_t3[BB * T2D * 64];
__device__ float  g_ck[SK * BB * T2D * 64];   // split-K partials (max layer)
__device__ float  g_part[2 * 1024 * 64];      // BN partials (sum | sumsq)
__device__ float  g_scale[64];
__device__ float  g_shift[64];
__device__ float  g_h[BB * 256];
__device__ float  g_a1[BB * 512];
__device__ float  g_a2[BB * 256];

__device__ __forceinline__ float ex2(float x) {
    float y;
    asm("ex2.approx.ftz.f32 %0, %1;" : "=f"(y) : "f"(x));
    return y;
}

// ---------------- point prep ----------------
__global__ void k_prep(const float* __restrict__ x) {
    int i = blockIdx.x * blockDim.x + threadIdx.x;
    if (i >= BB * NPTS) return;
    float a = x[3 * i], b = x[3 * i + 1], c = x[3 * i + 2];
    float n2 = a * a + b * b + c * c;
    g_xp[i] = make_float4(a * C2F, b * C2F, c * C2F, -C1F * n2);
}

// ---------------- gather E0 + rowsums of D_eval0 ----------------
__global__ void k_e0prep(const float* __restrict__ D0) {
    int q = blockIdx.x * blockDim.x + threadIdx.x;
    if (q >= QQ) return;
    const float* row = D0 + q * T0D;
    float s = 0.f;
    for (int t = 0; t < T0D; t++) s += row[t];
    g_rs0[q] = s;
    for (int j = 0; j < NSH; j++) g_E0[q * NSH + j] = row[c_pidx[j]];
}

// ---------------- shell densities ----------------
__global__ void __launch_bounds__(256) k_shell(const float* __restrict__ dirs) {
    __shared__ float4 sp[NPTS];  // 32 KB
    int b = blockIdx.y;
    int s = blockIdx.x * 256 + threadIdx.x;
    const float4* src = g_xp + b * NPTS;
    for (int i = threadIdx.x; i < NPTS; i += 256) sp[i] = src[i];
    __syncthreads();

    int shell = s >> 9;
    int j = s & 511;
    float r = c_radii[shell];
    const float* d = dirs + (size_t)(shell * SDIR + j) * 3;
    float cx = d[0] * r, cy = d[1] * r, cz = d[2] * r;
    float acc0 = 0.f, acc1 = 0.f;
#pragma unroll 8
    for (int i = 0; i < NPTS; i += 2) {
        float4 p = sp[i];
        float4 q = sp[i + 1];
        float t0 = fmaf(p.x, cx, fmaf(p.y, cy, fmaf(p.z, cz, p.w)));
        float t1 = fmaf(q.x, cx, fmaf(q.y, cy, fmaf(q.z, cz, q.w)));
        acc0 += ex2(t0);
        acc1 += ex2(t1);
    }
    float sc = ex2(-C1F * r * r) * (1.0f / (float)NPTS);
    g_f[b * NDIRS + s] = (acc0 + acc1) * sc;
}

// ---------------- SH projection, warp-per-output ----------------
__global__ void k_shproj(const float* __restrict__ A_sh) {
    int w = blockIdx.x * 8 + (threadIdx.x >> 5);
    int l = threadIdx.x & 31;
    int b = w / 108;
    int o = w % 108;
    int shell = o / NSH;
    int j = o % NSH;
    const float* arow = A_sh + j * SDIR;
    const float* f = g_f + b * NDIRS + shell * SDIR;
    float acc = 0.f;
#pragma unroll
    for (int s = l; s < SDIR; s += 32) acc = fmaf(arow[s], f[s], acc);
#pragma unroll
    for (int st = 16; st > 0; st >>= 1)
        acc += __shfl_xor_sync(0xffffffffu, acc, st);
    if (l == 0) g_sh[(b * NSH + j) * 3 + shell] = acc;
}

// ---------------- channel mix ----------------
__global__ void k_mix(const float* __restrict__ in, const float* __restrict__ W,
                      const float* __restrict__ bias, float* __restrict__ out,
                      int T, int Cin, int U) {
    int i = blockIdx.x * 256 + threadIdx.x;
    if (i >= BB * T * U) return;
    int u = i % U;
    int bt = i / U;
    const float* row = in + (size_t)bt * Cin;
    float acc = bias ? bias[u] : 0.f;
    for (int c = 0; c < Cin; c++) acc = fmaf(row[c], W[c * U + u], acc);
    out[i] = acc;
}

// ---------------- 2D register-tiled GEMM (split-K + fused BN-stats capable) ----------------
// C[z][bb][m][u] = sum_{k in slice z} A[m][k] * act(B[bb][k][u]) (+ rowsum[m]*bias[u])
// Block 256 threads (16x16), 4x4 outputs each; tile M=64 x NE=N*NB=64.
// klen>0: K-slice per blockIdx.z. statsOut!=null: per-block sum/sumsq partials.
template <int N, int NB>
__global__ void __launch_bounds__(256) k_gemm2(
    const float* __restrict__ A, const float* __restrict__ Bm, float* __restrict__ C,
    int M, int K,
    const float* __restrict__ sc, const float* __restrict__ sh,
    const float* __restrict__ rowsum, const float* __restrict__ bias,
    float* __restrict__ statsOut, int klen) {
    constexpr int NE = N * NB;      // 64
    __shared__ __align__(16) float As[32][72];
    __shared__ __align__(16) float Bs[32][NE];
    int t = threadIdx.x;
    int tx = t & 15, ty = t >> 4;
    int m0 = blockIdx.x * 64;
    int bgrp = blockIdx.y * NB;
    int kbase = 0, kend = K;
    if (klen > 0) {
        kbase = blockIdx.z * klen;
        kend = min(K, kbase + klen);
    }
    float acc[4][4];
#pragma unroll
    for (int i = 0; i < 4; i++)
#pragma unroll
        for (int jj = 0; jj < 4; jj++) acc[i][jj] = 0.f;

    for (int k0 = kbase; k0 < kend; k0 += 32) {
#pragma unroll
        for (int e = 0; e < 8; e++) {
            int idx = t + e * 256;
            int row = idx >> 5, col = idx & 31;
            int m = m0 + row, k = k0 + col;
            As[col][row] = (m < M && k < kend) ? A[(size_t)m * K + k] : 0.f;
        }
#pragma unroll
        for (int e = 0; e < (32 * NE) / 256; e++) {
            int idx = t + e * 256;
            int kk = idx / NE, uu = idx % NE;
            int k = k0 + kk;
            float v = 0.f;
            if (k < kend) {
                int bb = bgrp + uu / N;
                int u = uu % N;
                v = Bm[((size_t)bb * K + k) * N + u];
                if (sc) {
                    v = fmaf(v, sc[u], sh[u]);
                    v = fmaxf(v, 0.3f * v);
                }
            }
            Bs[kk][uu] = v;
        }
        __syncthreads();
#pragma unroll 8
        for (int kk = 0; kk < 32; kk++) {
            float4 a = *reinterpret_cast<const float4*>(&As[kk][ty * 4]);
            float4 bv = *reinterpret_cast<const float4*>(&Bs[kk][tx * 4]);
            float av[4] = {a.x, a.y, a.z, a.w};
            float bw[4] = {bv.x, bv.y, bv.z, bv.w};
#pragma unroll
            for (int i = 0; i < 4; i++)
#pragma unroll
                for (int jj = 0; jj < 4; jj++)
                    acc[i][jj] = fmaf(av[i], bw[jj], acc[i][jj]);
        }
        __syncthreads();
    }

    // epilogue (+ optional fused stats partials)
    int uu0 = tx * 4;
    int bb = bgrp + uu0 / N;
    int ub = uu0 % N;
    size_t cbase = ((size_t)blockIdx.z * BB + bb) * M;
    float ps[4] = {0.f, 0.f, 0.f, 0.f}, pq[4] = {0.f, 0.f, 0.f, 0.f};
#pragma unroll
    for (int i = 0; i < 4; i++) {
        int m = m0 + ty * 4 + i;
        if (m < M) {
            float rs = rowsum ? rowsum[m] : 0.f;
#pragma unroll
            for (int jj = 0; jj < 4; jj++) {
                float v = acc[i][jj];
                if (rowsum) v = fmaf(rs, bias[ub + jj], v);
                C[(cbase + m) * N + ub + jj] = v;
                ps[jj] += v;
                pq[jj] = fmaf(v, v, pq[jj]);
            }
        }
    }
    if (statsOut) {
        float* red = &As[0][0];   // reuse smem: need 2048 + 128 floats <= 2304
        __syncthreads();          // done reading As
#pragma unroll
        for (int jj = 0; jj < 4; jj++) {
            red[ty * 64 + uu0 + jj] = ps[jj];
            red[1024 + ty * 64 + uu0 + jj] = pq[jj];
        }
        __syncthreads();
        if (t < 64) {
            float s = 0.f, q = 0.f;
#pragma unroll
            for (int r = 0; r < 16; r++) {
                s += red[r * 64 + t];
                q += red[1024 + r * 64 + t];
            }
            red[2048 + t] = s;
            red[2112 + t] = q;
        }
        __syncthreads();
        if (t < N) {
            float s = 0.f, q = 0.f;
#pragma unroll
            for (int g = 0; g < NB; g++) {
                s += red[2048 + g * N + t];
                q += red[2112 + g * N + t];
            }
            int bid = blockIdx.y * gridDim.x + blockIdx.x;
            int nblk = gridDim.x * gridDim.y;
            statsOut[bid * N + t] = s;
            statsOut[nblk * N + bid * N + t] = q;
        }
    }
}

// ---------------- split-K reduce ----------------
__global__ void k_reduce_sk(const float* __restrict__ src, float* __restrict__ dst,
                            int n, int stride) {
    int i = blockIdx.x * 256 + threadIdx.x;
    if (i >= n) return;
    float s = 0.f;
#pragma unroll
    for (int z = 0; z < SK; z++) s += src[(size_t)z * stride + i];
    dst[i] = s;
}

// ---------------- BN finalize over per-block partials ----------------
__global__ void k_stats_fin(int U, int nblk, const float* __restrict__ g,
                            const float* __restrict__ be) {
    int u = blockIdx.x;
    int t = threadIdx.x;
    float s = 0.f, q = 0.f;
    for (int r = t; r < nblk; r += 256) {
        s += g_part[r * U + u];
        q += g_part[nblk * U + r * U + u];
    }
    __shared__ float ss[256], qq[256];
    ss[t] = s; qq[t] = q;
    __syncthreads();
    for (int st = 128; st > 0; st >>= 1) {
        if (t < st) { ss[t] += ss[t + st]; qq[t] += qq[t + st]; }
        __syncthreads();
    }
    if (t == 0) {
        const float inv = 1.0f / (float)(BB * QQ);
        float m = ss[0] * inv;
        float var = qq[0] * inv - m * m;
        float rs = rsqrtf(var + 1e-3f);
        float scv = rs * g[u];
        g_scale[u] = scv;
        g_shift[u] = be[u] - m * scv;
    }
}

// ---------------- degree-wise norms -> h[b,256] ----------------
__global__ void k_norm() {
    int b = blockIdx.x;
    int t = threadIdx.x;
    int blk = t >> 6;
    int u = t & 63;
    int off, sz;
    if (blk == 0)      { off = 0;  sz = 1; }
    else if (blk == 1) { off = 1;  sz = 9; }
    else if (blk == 2) { off = 10; sz = 25; }
    else               { off = 35; sz = 49; }
    const float* y = g_t3 + (size_t)b * T2D * 64;
    float s = 0.f;
    for (int r = 0; r < sz; r++) {
        float v = y[(off + r) * 64 + u];
        s = fmaf(v, v, s);
    }
    g_h[b * 256 + t] = sqrtf(s);
}

// ---------------- dense FC ----------------
__global__ void k_fc(const float* __restrict__ in, const float* __restrict__ W,
                     const float* __restrict__ bias, float* __restrict__ out,
                     int IN, int OUT) {
    __shared__ float s[512];
    int b = blockIdx.x;
    for (int i = threadIdx.x; i < IN; i += blockDim.x) s[i] = in[b * IN + i];
    __syncthreads();
    int j = threadIdx.x;
    if (j < OUT) {
        float acc = bias[j];
        for (int i = 0; i < IN; i++) acc = fmaf(s[i], W[i * OUT + j], acc);
        out[b * OUT + j] = acc;
    }
}

// ---------------- batch BN + ReLU, in place ----------------
__global__ void k_bnrelu(float* __restrict__ a, const float* __restrict__ g,
                         const float* __restrict__ be, int F) {
    int j = blockIdx.x;
    int b = threadIdx.x;  // 64
    float v = a[b * F + j];
    __shared__ float ss[64], qq[64];
    __shared__ float sm, sr;
    ss[b] = v; qq[b] = v * v;
    __syncthreads();
    for (int st = 32; st > 0; st >>= 1) {
        if (b < st) { ss[b] += ss[b + st]; qq[b] += qq[b + st]; }
        __syncthreads();
    }
    if (b == 0) {
        float m = ss[0] * (1.0f / 64.0f);
        float var = qq[0] * (1.0f / 64.0f) - m * m;
        sm = m;
        sr = rsqrtf(var + 1e-3f);
    }
    __syncthreads();
    float y = (v - sm) * sr * g[j] + be[j];
    a[b * F + j] = y > 0.f ? y : 0.f;
}

// ---------------- output head + softmax ----------------
__global__ void k_out(const float* __restrict__ Wout, const float* __restrict__ bout,
                      float* __restrict__ out) {
    int b = blockIdx.x;
    __shared__ float h[256];
    __shared__ float lg[40];
    for (int i = threadIdx.x; i < 256; i += 64) h[i] = g_a2[b * 256 + i];
    __syncthreads();
    if (threadIdx.x < 40) {
        float acc = bout[threadIdx.x];
        for (int i = 0; i < 256; i++) acc = fmaf(h[i], Wout[i * 40 + threadIdx.x], acc);
        lg[threadIdx.x] = acc;
    }
    __syncthreads();
    if (threadIdx.x == 0) {
        float mx = -1e30f;
        for (int i = 0; i < 40; i++) mx = fmaxf(mx, lg[i]);
        float s = 0.f;
        for (int i = 0; i < 40; i++) {
            float e = __expf(lg[i] - mx);
            lg[i] = e;
            s += e;
        }
        float inv = 1.f / s;
        for (int i = 0; i < 40; i++) out[b * 40 + i] = lg[i] * inv;
    }
}

// ---------------- launch ----------------
extern "C" void kernel_launch(void* const* d_in, const int* in_sizes, int n_in,
                              void* d_out, int out_size) {
    const float* x          = (const float*)d_in[0];
    const float* shell_dirs = (const float*)d_in[1];
    const float* A_sh       = (const float*)d_in[2];
    const float* D_eval0    = (const float*)d_in[3];
    const float* D_eval1    = (const float*)d_in[4];
    const float* D_eval2    = (const float*)d_in[5];
    const float* D_coef1    = (const float*)d_in[6];
    const float* D_coef2    = (const float*)d_in[7];
    const float* D_coefL    = (const float*)d_in[8];
    const float* W0 = (const float*)d_in[9];   const float* b0 = (const float*)d_in[10];
    const float* W1 = (const float*)d_in[11];  const float* b1 = (const float*)d_in[12];
    const float* W2 = (const float*)d_in[13];  const float* b2 = (const float*)d_in[14];
    const float* g0 = (const float*)d_in[15];  const float* be0 = (const float*)d_in[16];
    const float* g1 = (const float*)d_in[17];  const float* be1 = (const float*)d_in[18];
    const float* g2 = (const float*)d_in[19];  const float* be2 = (const float*)d_in[20];
    const float* Wfc1 = (const float*)d_in[21]; const float* bfc1 = (const float*)d_in[22];
    const float* gfc1 = (const float*)d_in[23]; const float* befc1 = (const float*)d_in[24];
    const float* Wfc2 = (const float*)d_in[25]; const float* bfc2 = (const float*)d_in[26];
    const float* gfc2 = (const float*)d_in[27]; const float* befc2 = (const float*)d_in[28];
    const float* Wout = (const float*)d_in[29]; const float* bout = (const float*)d_in[30];
    float* out = (float*)d_out;

    float *pE0, *prs0, *psh, *pz0, *pY, *pt1, *pz1, *pt2, *pz2, *pt3, *pck,
          *ppart, *psc, *pshf, *ph, *pa1, *pa2;
    cudaGetSymbolAddress((void**)&pE0, g_E0);
    cudaGetSymbolAddress((void**)&prs0, g_rs0);
    cudaGetSymbolAddress((void**)&psh, g_sh);
    cudaGetSymbolAddress((void**)&pz0, g_z0);
    cudaGetSymbolAddress((void**)&pY, g_Y);
    cudaGetSymbolAddress((void**)&pt1, g_t1);
    cudaGetSymbolAddress((void**)&pz1, g_z1);
    cudaGetSymbolAddress((void**)&pt2, g_t2);
    cudaGetSymbolAddress((void**)&pz2, g_z2);
    cudaGetSymbolAddress((void**)&pt3, g_t3);
    cudaGetSymbolAddress((void**)&pck, g_ck);
    cudaGetSymbolAddress((void**)&ppart, g_part);
    cudaGetSymbolAddress((void**)&psc, g_scale);
    cudaGetSymbolAddress((void**)&pshf, g_shift);
    cudaGetSymbolAddress((void**)&ph, g_h);
    cudaGetSymbolAddress((void**)&pa1, g_a1);
    cudaGetSymbolAddress((void**)&pa2, g_a2);

    // shell embedding
    k_prep<<<(BB * NPTS + 255) / 256, 256>>>(x);
    k_e0prep<<<4, 256>>>(D_eval0);
    k_shell<<<dim3(6, BB), 256>>>(shell_dirs);
    k_shproj<<<864, 256>>>(A_sh);

    // layer 0
    k_mix<<<(BB * NSH * 16 + 255) / 256, 256>>>(psh, W0, nullptr, pz0, NSH, 3, 16);
    k_gemm2<16, 4><<<dim3(16, 16), 256>>>(pE0, pz0, pY, QQ, NSH, nullptr, nullptr,
                                          prs0, b0, ppart, 0);
    k_stats_fin<<<16, 256>>>(16, 256, g0, be0);
    k_gemm2<16, 4><<<dim3(3, 16, SK), 256>>>(D_coef1, pY, pck, T1D, QQ, psc, pshf,
                                             nullptr, nullptr, nullptr, QQ / SK);
    k_reduce_sk<<<(BB * T1D * 16 + 255) / 256, 256>>>(pck, pt1, BB * T1D * 16, BB * T1D * 16);

    // layer 1
    k_mix<<<(BB * T1D * 32 + 255) / 256, 256>>>(pt1, W1, b1, pz1, T1D, 16, 32);
    k_gemm2<32, 2><<<dim3(16, 32), 256>>>(D_eval1, pz1, pY, QQ, T1D, nullptr, nullptr,
                                          nullptr, nullptr, ppart, 0);
    k_stats_fin<<<32, 256>>>(32, 512, g1, be1);
    k_gemm2<32, 2><<<dim3(2, 32, SK), 256>>>(D_coef2, pY, pck, T2D, QQ, psc, pshf,
                                             nullptr, nullptr, nullptr, QQ / SK);
    k_reduce_sk<<<(BB * T2D * 32 + 255) / 256, 256>>>(pck, pt2, BB * T2D * 32, BB * T2D * 32);

    // layer 2
    k_mix<<<(BB * T2D * 64 + 255) / 256, 256>>>(pt2, W2, b2, pz2, T2D, 32, 64);
    k_gemm2<64, 1><<<dim3(16, 64), 256>>>(D_eval2, pz2, pY, QQ, T2D, nullptr, nullptr,
                                          nullptr, nullptr, ppart, 0);
    k_stats_fin<<<64, 256>>>(64, 1024, g2, be2);
    k_gemm2<64, 1><<<dim3(2, 64, SK), 256>>>(D_coefL, pY, pck, T2D, QQ, psc, pshf,
                                             nullptr, nullptr, nullptr, QQ / SK);
    k_reduce_sk<<<(BB * T2D * 64 + 255) / 256, 256>>>(pck, pt3, BB * T2D * 64, BB * T2D * 64);

    // pooling + head
    k_norm<<<BB, 256>>>();
    k_fc<<<BB, 512>>>(ph, Wfc1, bfc1, pa1, 256, 512);
    k_bnrelu<<<512, 64>>>(pa1, gfc1, befc1, 512);
    k_fc<<<BB, 256>>>(pa1, Wfc2, bfc2, pa2, 512, 256);
    k_bnrelu<<<256, 64>>>(pa2, gfc2, befc2, 256);
    k_out<<<BB, 64>>>(Wout, bout, out);
}